// round 11
// baseline (speedup 1.0000x reference)
#include <cuda_runtime.h>
#include <math.h>

// ---------------- scratch (no allocation allowed) ----------------
#define MAXN   262144
#define SCAN_BLK 512           // threads per scan block
#define TILE   2048            // segments per scan tile (4 per thread)
#define MAX_NB 128
#define FLAG_AGG  0x10000000
#define FLAG_INCL 0x20000000
#define VMASK     0x0FFFFFFF
#define FULL      0xffffffffu
__device__ __align__(16) int2 g_meta[MAXN];  // (exclusive offset, count) per segment
__device__ __align__(16) int2 g_win[MAXN];   // (winner row, dist bits) per segment
__device__ int    g_state[MAX_NB];   // decoupled-lookback state (zero-init, reset at finalize)
__device__ double g_acc[4];          // lp, la, lw, ls sums
__device__ int    g_done = 0;        // completion counter for folded finalize

// ------ kernel 1: single-pass scan, warp-parallel lookback (<=128 blocks) -----
__global__ void __launch_bounds__(SCAN_BLK) k_scan(const int* __restrict__ counts, int N) {
    __shared__ int wsum[16];
    __shared__ int s_ex;
    int tid = threadIdx.x, lane = tid & 31, w = tid >> 5;
    int base4 = blockIdx.x * TILE + tid * 4;

    int4 v = make_int4(0, 0, 0, 0);
    if (base4 + 3 < N) v = *(const int4*)(counts + base4);
    else {
        if (base4 + 0 < N) v.x = counts[base4 + 0];
        if (base4 + 1 < N) v.y = counts[base4 + 1];
        if (base4 + 2 < N) v.z = counts[base4 + 2];
        if (base4 + 3 < N) v.w = counts[base4 + 3];
    }
    int s = v.x + v.y + v.z + v.w;

    // warp inclusive scan of per-thread sums
    int si = s;
    #pragma unroll
    for (int o = 1; o < 32; o <<= 1) {
        int t = __shfl_up_sync(FULL, si, o);
        if (lane >= o) si += t;
    }
    if (lane == 31) wsum[w] = si;
    __syncthreads();
    if (w == 0) {
        int ws = (lane < 16) ? wsum[lane] : 0;
        int wi = ws;
        #pragma unroll
        for (int o = 1; o < 16; o <<= 1) {
            int t = __shfl_up_sync(FULL, wi, o);
            if (lane >= o) wi += t;
        }
        if (lane < 16) wsum[lane] = wi - ws;         // exclusive warp offset
        int total = __shfl_sync(FULL, wi, 15);       // tile aggregate

        if (lane == 0) {                             // publish
            if (blockIdx.x == 0) atomicExch(&g_state[0], total | FLAG_INCL);
            else                 atomicExch(&g_state[blockIdx.x], total | FLAG_AGG);
        }
        int ex = 0;
        if (blockIdx.x > 0) {                        // warp-parallel lookback
            int p = (int)blockIdx.x - 1;
            while (true) {
                int idx = p - lane;
                int st = (idx >= 0) ? atomicAdd(&g_state[idx], 0) : FLAG_INCL;
                while (__any_sync(FULL, st == 0))
                    st = (idx >= 0) ? atomicAdd(&g_state[idx], 0) : FLAG_INCL;
                unsigned im = __ballot_sync(FULL, (st & FLAG_INCL) != 0);
                if (im) {
                    int k = __ffs(im) - 1;           // nearest inclusive predecessor
                    int contrib = (lane <= k) ? (st & VMASK) : 0;
                    ex += __reduce_add_sync(FULL, contrib);
                    break;
                } else {
                    ex += __reduce_add_sync(FULL, st & VMASK);
                    p -= 32;
                }
            }
            if (lane == 0) atomicExch(&g_state[blockIdx.x], (ex + total) | FLAG_INCL);
        } else if (lane == 0) {
            g_acc[0] = 0.0; g_acc[1] = 0.0; g_acc[2] = 0.0; g_acc[3] = 0.0;
        }
        if (lane == 0) s_ex = ex;
    }
    __syncthreads();

    int base = s_ex + wsum[w] + (si - s);            // global exclusive prefix
    if (base4 + 3 < N) {
        int4 m0 = make_int4(base,             v.x, base + v.x,            v.y);
        int4 m1 = make_int4(base + v.x + v.y, v.z, base + v.x + v.y + v.z, v.w);
        *(int4*)(&g_meta[base4])     = m0;
        *(int4*)(&g_meta[base4 + 2]) = m1;
    } else {
        int b = base;
        if (base4 + 0 < N) { g_meta[base4 + 0] = make_int2(b, v.x); b += v.x; }
        if (base4 + 1 < N) { g_meta[base4 + 1] = make_int2(b, v.y); b += v.y; }
        if (base4 + 2 < N) { g_meta[base4 + 2] = make_int2(b, v.z); }
    }
}

// ---------------- pass 1: warp-per-segment argmin only ------------------------
__device__ __forceinline__ void p1_load(
    const float* __restrict__ pred, const float* __restrict__ gt,
    int s, int M, int lane, unsigned& db, int& off, int& cnt)
{
    int2 mc = g_meta[s];
    off = mc.x; cnt = mc.y;
    float2 p01 = *(const float2*)(pred + (size_t)s * 6);
    int r = off + ((lane < cnt) ? lane : 0);
    r = min(r, M - 1); r = max(r, 0);
    float2 g01 = *(const float2*)(gt + (size_t)r * 6);
    float dx = p01.x - g01.x, dy = p01.y - g01.y;
    float d  = dx * dx + dy * dy;
    db = (lane < cnt) ? __float_as_uint(d) : 0x7f800000u;
}

__device__ __forceinline__ void p1_finish(int s, int lane, unsigned db, int off, int cnt)
{
    unsigned mn   = __reduce_min_sync(FULL, db);       // min dist bits (nonneg fp)
    unsigned mask = __ballot_sync(FULL, db == mn);     // lowest lane = ref tie-break
    if (lane == 0 && cnt > 0)
        g_win[s] = make_int2(off + __ffs(mask) - 1, (int)mn);
}

__global__ void __launch_bounds__(256) k_pass1(
    const float* __restrict__ pred,
    const float* __restrict__ gt,
    int N, int M)
{
    const int lane   = threadIdx.x & 31;
    const int warpId = (blockIdx.x * blockDim.x + threadIdx.x) >> 5;
    const int nWarps = (gridDim.x * blockDim.x) >> 5;

    int s = warpId;
    for (; s + 3 * nWarps < N; s += 4 * nWarps) {
        unsigned d0, d1, d2, d3; int o0, c0, o1, c1, o2, c2, o3, c3;
        p1_load(pred, gt, s,              M, lane, d0, o0, c0);   // 4 gt loads in flight
        p1_load(pred, gt, s +     nWarps, M, lane, d1, o1, c1);
        p1_load(pred, gt, s + 2 * nWarps, M, lane, d2, o2, c2);
        p1_load(pred, gt, s + 3 * nWarps, M, lane, d3, o3, c3);
        p1_finish(s,              lane, d0, o0, c0);
        p1_finish(s +     nWarps, lane, d1, o1, c1);
        p1_finish(s + 2 * nWarps, lane, d2, o2, c2);
        p1_finish(s + 3 * nWarps, lane, d3, o3, c3);
    }
    for (; s < N; s += nWarps) {
        unsigned d0; int o0, c0;
        p1_load(pred, gt, s, M, lane, d0, o0, c0);
        p1_finish(s, lane, d0, o0, c0);
    }
}

// ---------------- pass 2: thread-per-segment losses + finalize ----------------
__global__ void __launch_bounds__(256) k_pass2(
    const float* __restrict__ pred,
    const float* __restrict__ gt,
    float* __restrict__ out,
    int N)
{
    const int lane   = threadIdx.x & 31;
    const int wInBlk = threadIdx.x >> 5;
    int s = blockIdx.x * blockDim.x + threadIdx.x;

    float l0 = 0.f, l1 = 0.f, l2 = 0.f, l3 = 0.f;
    if (s < N) {
        int cnt = g_meta[s].y;                 // coalesced
        if (cnt > 0) {
            int2 wv = g_win[s];                // coalesced
            float dmin = __uint_as_float((unsigned)wv.y);
            l0 = 1.0f - __expf(dmin * (-1.0f / 0.045f));   // 2*sigma^2 = 0.045

            const float* pr = pred + (size_t)s * 6;
            const float* gr = gt + (size_t)wv.x * 6;
            float2 p23 = *(const float2*)(pr + 2);
            float2 p45 = *(const float2*)(pr + 4);
            float2 g23 = *(const float2*)(gr + 2);
            float2 g45 = *(const float2*)(gr + 4);

            l1 = fabsf(p23.x - g23.x) + fabsf(p23.y - g23.y);
            float dd = p45.x - g45.x, ad = fabsf(dd);
            l2 = (ad < 1.0f) ? 0.5f * dd * dd : ad - 0.5f;
            float x = p45.y, t = g45.y;
            if (t > 0.0f) {
                float z = __expf(-fabsf(x));
                l3 = fmaxf(x, 0.0f) - x * t + __logf(1.0f + z);
            }
        }
    }

    // warp reduce
    #pragma unroll
    for (int o = 16; o; o >>= 1) {
        l0 += __shfl_xor_sync(FULL, l0, o);
        l1 += __shfl_xor_sync(FULL, l1, o);
        l2 += __shfl_xor_sync(FULL, l2, o);
        l3 += __shfl_xor_sync(FULL, l3, o);
    }

    __shared__ float sh[8][4];
    if (lane == 0) {
        sh[wInBlk][0] = l0; sh[wInBlk][1] = l1;
        sh[wInBlk][2] = l2; sh[wInBlk][3] = l3;
    }
    __syncthreads();
    if (threadIdx.x == 0) {
        float b0 = 0.f, b1 = 0.f, b2 = 0.f, b3 = 0.f;
        int nw = blockDim.x >> 5;
        for (int w = 0; w < nw; w++) {
            b0 += sh[w][0]; b1 += sh[w][1]; b2 += sh[w][2]; b3 += sh[w][3];
        }
        atomicAdd(&g_acc[0], (double)b0);
        atomicAdd(&g_acc[1], (double)b1);
        atomicAdd(&g_acc[2], (double)b2);
        atomicAdd(&g_acc[3], (double)b3);
        __threadfence();
        int done = atomicAdd(&g_done, 1);
        if (done == (int)gridDim.x - 1) {
            g_done = 0;                               // reset for next replay
            #pragma unroll
            for (int i = 0; i < MAX_NB; i++) g_state[i] = 0;   // reset lookback state
            double inv = 1.0 / (double)N;
            double lp = ((volatile double*)g_acc)[0] * inv;
            double la = ((volatile double*)g_acc)[1] * inv;
            double lw = ((volatile double*)g_acc)[2] * inv;
            double ls = ((volatile double*)g_acc)[3] * inv;
            out[0] = (float)lp;
            out[1] = (float)la;
            out[2] = (float)lw;
            out[3] = (float)ls;
            out[4] = (float)(lp + la + lw + 0.5 * ls);
        }
    }
}

extern "C" void kernel_launch(void* const* d_in, const int* in_sizes, int n_in,
                              void* d_out, int out_size) {
    const float* pred   = (const float*)d_in[0];
    const float* gt     = (const float*)d_in[1];
    const int*   counts = (const int*)d_in[2];
    float* out = (float*)d_out;

    int N = in_sizes[2];
    if (N > MAXN) N = MAXN;              // scratch guard (contract: N == 262144)
    int M = in_sizes[1] / 6;             // total gt rows
    int NB = (N + TILE - 1) / TILE;      // <= 128 tiles (all resident: lookback safe)

    k_scan<<<NB, SCAN_BLK>>>(counts, N);
    k_pass1<<<2048, 256>>>(pred, gt, N, M);
    k_pass2<<<(N + 255) / 256, 256>>>(pred, gt, out, N);
}

// round 12
// speedup vs baseline: 1.1034x; 1.1034x over previous
#include <cuda_runtime.h>
#include <math.h>

// ---------------- scratch (no allocation allowed) ----------------
#define MAXN   262144
#define CHUNK  128                     // segments per pass1 block
#define MAXC   (MAXN / CHUNK)          // 2048 chunks
#define FULL   0xffffffffu
__device__ __align__(16) int2 g_win[MAXN];   // (winner row + 1 or 0, dist bits)
__device__ int    g_csum[MAXC];      // per-chunk count sums
__device__ int    g_cbase[MAXC];     // exclusive chunk bases
__device__ double g_acc[4];          // lp, la, lw, ls sums
__device__ int    g_done = 0;        // completion counter for folded finalize

// ------ kernel A: per-chunk sums (one warp per chunk, int4 + redux) -----------
__global__ void __launch_bounds__(256) k_csum(const int* __restrict__ counts, int N, int NC) {
    int w    = (blockIdx.x * blockDim.x + threadIdx.x) >> 5;   // global warp = chunk
    int lane = threadIdx.x & 31;
    if (w >= NC) return;
    int base = w * CHUNK + lane * 4;
    int4 v = make_int4(0, 0, 0, 0);
    if (base + 3 < N) v = *(const int4*)(counts + base);
    else {
        if (base + 0 < N) v.x = counts[base + 0];
        if (base + 1 < N) v.y = counts[base + 1];
        if (base + 2 < N) v.z = counts[base + 2];
        if (base + 3 < N) v.w = counts[base + 3];
    }
    int s = __reduce_add_sync(FULL, v.x + v.y + v.z + v.w);
    if (lane == 0) g_csum[w] = s;
}

// ------ kernel B: scan chunk sums (single block, 512 thr x 4) -----------------
__global__ void __launch_bounds__(512) k_cscan(int NC) {
    __shared__ int wsum[16];
    int tid = threadIdx.x, lane = tid & 31, w = tid >> 5;
    int i0 = tid * 4;
    int v0 = (i0 + 0 < NC) ? g_csum[i0 + 0] : 0;
    int v1 = (i0 + 1 < NC) ? g_csum[i0 + 1] : 0;
    int v2 = (i0 + 2 < NC) ? g_csum[i0 + 2] : 0;
    int v3 = (i0 + 3 < NC) ? g_csum[i0 + 3] : 0;
    int s = v0 + v1 + v2 + v3;

    int si = s;
    #pragma unroll
    for (int o = 1; o < 32; o <<= 1) {
        int t = __shfl_up_sync(FULL, si, o);
        if (lane >= o) si += t;
    }
    if (lane == 31) wsum[w] = si;
    __syncthreads();
    if (w == 0) {
        int ws = (lane < 16) ? wsum[lane] : 0;
        int wi = ws;
        #pragma unroll
        for (int o = 1; o < 16; o <<= 1) {
            int t = __shfl_up_sync(FULL, wi, o);
            if (lane >= o) wi += t;
        }
        if (lane < 16) wsum[lane] = wi - ws;   // exclusive warp offset
    }
    __syncthreads();

    int b = wsum[w] + (si - s);                // global exclusive base of thread's 4
    if (i0 + 0 < NC) g_cbase[i0 + 0] = b;       b += v0;
    if (i0 + 1 < NC) g_cbase[i0 + 1] = b;       b += v1;
    if (i0 + 2 < NC) g_cbase[i0 + 2] = b;       b += v2;
    if (i0 + 3 < NC) g_cbase[i0 + 3] = b;
    if (tid < 4) g_acc[tid] = 0.0;
}

// ------ pass 1: block = 128 contiguous segments; local scan + warp argmin -----
__device__ __forceinline__ void p1_seg(
    const float* __restrict__ pred, const float* __restrict__ gt,
    const int* __restrict__ s_off, int gbase, int j, int M, int N, int lane,
    unsigned& db, int& off, int& cnt, float2& p01, int& r)
{
    off = s_off[j]; cnt = s_off[j + 1] - off;
    int s = gbase + j;
    p01 = (s < N) ? *(const float2*)(pred + (size_t)s * 6) : make_float2(0.f, 0.f);
    r = off + ((lane < cnt) ? lane : 0);
    r = min(r, M - 1);
}

__global__ void __launch_bounds__(256) k_pass1(
    const float* __restrict__ pred,
    const float* __restrict__ gt,
    const int*   __restrict__ counts,
    int N, int M)
{
    __shared__ int s_off[CHUNK + 1];
    __shared__ int s_wtot[4];
    const int tid  = threadIdx.x;
    const int lane = tid & 31;
    const int gbase = blockIdx.x * CHUNK;

    // local exclusive scan of this block's 128 counts
    if (tid < CHUNK) {
        int w = tid >> 5;
        int g = gbase + tid;
        int c = (g < N) ? counts[g] : 0;
        int inc = c;
        #pragma unroll
        for (int o = 1; o < 32; o <<= 1) {
            int t = __shfl_up_sync(FULL, inc, o);
            if (lane >= o) inc += t;
        }
        if (lane == 31) s_wtot[w] = inc;
        __syncthreads();
        int woff = 0;
        #pragma unroll
        for (int i = 0; i < 4; i++) woff += (i < w) ? s_wtot[i] : 0;
        int cbase = g_cbase[blockIdx.x];
        s_off[tid] = cbase + woff + inc - c;
        if (tid == CHUNK - 1) s_off[CHUNK] = cbase + woff + inc;
    } else {
        __syncthreads();
    }
    __syncthreads();

    // 8 warps x 16 consecutive segments each
    const int wInBlk = tid >> 5;
    const int wbase  = wInBlk * 16;

    #pragma unroll
    for (int k = 0; k < 16; k += 2) {
        unsigned db0, db1; int off0, cnt0, off1, cnt1, r0, r1; float2 p0, p1;
        p1_seg(pred, gt, s_off, gbase, wbase + k,     M, N, lane, db0, off0, cnt0, p0, r0);
        p1_seg(pred, gt, s_off, gbase, wbase + k + 1, M, N, lane, db1, off1, cnt1, p1, r1);

        float2 q0 = *(const float2*)(gt + (size_t)r0 * 6);   // 2 loads in flight
        float2 q1 = *(const float2*)(gt + (size_t)r1 * 6);

        float dx0 = p0.x - q0.x, dy0 = p0.y - q0.y;
        float dx1 = p1.x - q1.x, dy1 = p1.y - q1.y;
        db0 = (lane < cnt0) ? __float_as_uint(dx0 * dx0 + dy0 * dy0) : 0x7f800000u;
        db1 = (lane < cnt1) ? __float_as_uint(dx1 * dx1 + dy1 * dy1) : 0x7f800000u;

        unsigned mn0 = __reduce_min_sync(FULL, db0);
        unsigned mk0 = __ballot_sync(FULL, db0 == mn0);   // lowest lane = ref tie-break
        unsigned mn1 = __reduce_min_sync(FULL, db1);
        unsigned mk1 = __ballot_sync(FULL, db1 == mn1);

        if (lane == 0) {
            int s0 = gbase + wbase + k, s1 = s0 + 1;
            if (s0 < N) g_win[s0] = make_int2(cnt0 > 0 ? off0 + __ffs(mk0) : 0, (int)mn0);
            if (s1 < N) g_win[s1] = make_int2(cnt1 > 0 ? off1 + __ffs(mk1) : 0, (int)mn1);
        }
    }
}

// ---------------- pass 2: thread-per-segment losses + finalize ----------------
__global__ void __launch_bounds__(256) k_pass2(
    const float* __restrict__ pred,
    const float* __restrict__ gt,
    float* __restrict__ out,
    int N)
{
    const int lane   = threadIdx.x & 31;
    const int wInBlk = threadIdx.x >> 5;
    int s = blockIdx.x * blockDim.x + threadIdx.x;

    float l0 = 0.f, l1 = 0.f, l2 = 0.f, l3 = 0.f;
    if (s < N) {
        int2 wv = g_win[s];                    // coalesced
        if (wv.x > 0) {
            int row = wv.x - 1;
            float dmin = __uint_as_float((unsigned)wv.y);
            l0 = 1.0f - __expf(dmin * (-1.0f / 0.045f));   // 2*sigma^2 = 0.045

            const float* pr = pred + (size_t)s * 6;
            const float* gr = gt + (size_t)row * 6;
            float2 p23 = *(const float2*)(pr + 2);
            float2 p45 = *(const float2*)(pr + 4);
            float2 g23 = *(const float2*)(gr + 2);
            float2 g45 = *(const float2*)(gr + 4);

            l1 = fabsf(p23.x - g23.x) + fabsf(p23.y - g23.y);
            float dd = p45.x - g45.x, ad = fabsf(dd);
            l2 = (ad < 1.0f) ? 0.5f * dd * dd : ad - 0.5f;
            float x = p45.y, t = g45.y;
            if (t > 0.0f) {
                float z = __expf(-fabsf(x));
                l3 = fmaxf(x, 0.0f) - x * t + __logf(1.0f + z);
            }
        }
    }

    // warp reduce
    #pragma unroll
    for (int o = 16; o; o >>= 1) {
        l0 += __shfl_xor_sync(FULL, l0, o);
        l1 += __shfl_xor_sync(FULL, l1, o);
        l2 += __shfl_xor_sync(FULL, l2, o);
        l3 += __shfl_xor_sync(FULL, l3, o);
    }

    __shared__ float sh[8][4];
    if (lane == 0) {
        sh[wInBlk][0] = l0; sh[wInBlk][1] = l1;
        sh[wInBlk][2] = l2; sh[wInBlk][3] = l3;
    }
    __syncthreads();
    if (threadIdx.x == 0) {
        float b0 = 0.f, b1 = 0.f, b2 = 0.f, b3 = 0.f;
        int nw = blockDim.x >> 5;
        for (int w = 0; w < nw; w++) {
            b0 += sh[w][0]; b1 += sh[w][1]; b2 += sh[w][2]; b3 += sh[w][3];
        }
        atomicAdd(&g_acc[0], (double)b0);
        atomicAdd(&g_acc[1], (double)b1);
        atomicAdd(&g_acc[2], (double)b2);
        atomicAdd(&g_acc[3], (double)b3);
        __threadfence();
        int done = atomicAdd(&g_done, 1);
        if (done == (int)gridDim.x - 1) {
            g_done = 0;                               // reset for next replay
            double inv = 1.0 / (double)N;
            double lp = ((volatile double*)g_acc)[0] * inv;
            double la = ((volatile double*)g_acc)[1] * inv;
            double lw = ((volatile double*)g_acc)[2] * inv;
            double ls = ((volatile double*)g_acc)[3] * inv;
            out[0] = (float)lp;
            out[1] = (float)la;
            out[2] = (float)lw;
            out[3] = (float)ls;
            out[4] = (float)(lp + la + lw + 0.5 * ls);
        }
    }
}

extern "C" void kernel_launch(void* const* d_in, const int* in_sizes, int n_in,
                              void* d_out, int out_size) {
    const float* pred   = (const float*)d_in[0];
    const float* gt     = (const float*)d_in[1];
    const int*   counts = (const int*)d_in[2];
    float* out = (float*)d_out;

    int N = in_sizes[2];
    if (N > MAXN) N = MAXN;              // scratch guard (contract: N == 262144)
    int M = in_sizes[1] / 6;             // total gt rows
    int NC = (N + CHUNK - 1) / CHUNK;    // chunks (2048)

    k_csum <<<(NC + 7) / 8, 256>>>(counts, N, NC);      // 8 warps/block = 8 chunks
    k_cscan<<<1, 512>>>(NC);
    k_pass1<<<NC, 256>>>(pred, gt, counts, N, M);
    k_pass2<<<(N + 255) / 256, 256>>>(pred, gt, out, N);
}

// round 13
// speedup vs baseline: 1.3018x; 1.1799x over previous
#include <cuda_runtime.h>
#include <math.h>

// ---------------- scratch (no allocation allowed) ----------------
#define MAXN   262144
#define CHUNK  128                     // segments per pass1 block
#define MAXC   (MAXN / CHUNK)          // 2048 chunks
#define FULL   0xffffffffu
__device__ __align__(16) int2 g_win[MAXN];   // (winner row + 1 or 0, dist bits)
__device__ int    g_csum[MAXC];      // per-chunk count sums
__device__ int    g_cbase[MAXC];     // exclusive chunk bases
__device__ double g_acc[4];          // lp, la, lw, ls sums
__device__ int    g_done = 0;        // completion counter for folded finalize

// ------ kernel A: per-chunk sums (one warp per chunk, int4 + redux) -----------
__global__ void __launch_bounds__(256) k_csum(const int* __restrict__ counts, int N, int NC) {
    int w    = (blockIdx.x * blockDim.x + threadIdx.x) >> 5;   // global warp = chunk
    int lane = threadIdx.x & 31;
    if (w >= NC) return;
    int base = w * CHUNK + lane * 4;
    int4 v = make_int4(0, 0, 0, 0);
    if (base + 3 < N) v = *(const int4*)(counts + base);
    else {
        if (base + 0 < N) v.x = counts[base + 0];
        if (base + 1 < N) v.y = counts[base + 1];
        if (base + 2 < N) v.z = counts[base + 2];
        if (base + 3 < N) v.w = counts[base + 3];
    }
    int s = __reduce_add_sync(FULL, v.x + v.y + v.z + v.w);
    if (lane == 0) g_csum[w] = s;
}

// ------ kernel B: scan chunk sums (single block, 512 thr x 4) -----------------
__global__ void __launch_bounds__(512) k_cscan(int NC) {
    __shared__ int wsum[16];
    int tid = threadIdx.x, lane = tid & 31, w = tid >> 5;
    int i0 = tid * 4;
    int v0 = (i0 + 0 < NC) ? g_csum[i0 + 0] : 0;
    int v1 = (i0 + 1 < NC) ? g_csum[i0 + 1] : 0;
    int v2 = (i0 + 2 < NC) ? g_csum[i0 + 2] : 0;
    int v3 = (i0 + 3 < NC) ? g_csum[i0 + 3] : 0;
    int s = v0 + v1 + v2 + v3;

    int si = s;
    #pragma unroll
    for (int o = 1; o < 32; o <<= 1) {
        int t = __shfl_up_sync(FULL, si, o);
        if (lane >= o) si += t;
    }
    if (lane == 31) wsum[w] = si;
    __syncthreads();
    if (w == 0) {
        int ws = (lane < 16) ? wsum[lane] : 0;
        int wi = ws;
        #pragma unroll
        for (int o = 1; o < 16; o <<= 1) {
            int t = __shfl_up_sync(FULL, wi, o);
            if (lane >= o) wi += t;
        }
        if (lane < 16) wsum[lane] = wi - ws;   // exclusive warp offset
    }
    __syncthreads();

    int b = wsum[w] + (si - s);                // global exclusive base of thread's 4
    if (i0 + 0 < NC) g_cbase[i0 + 0] = b;       b += v0;
    if (i0 + 1 < NC) g_cbase[i0 + 1] = b;       b += v1;
    if (i0 + 2 < NC) g_cbase[i0 + 2] = b;       b += v2;
    if (i0 + 3 < NC) g_cbase[i0 + 3] = b;
    if (tid < 4) g_acc[tid] = 0.0;
}

// ------ pass 1: block = 128 contiguous segments; local scan + warp argmin -----
__device__ __forceinline__ void p1_seg(
    const float* __restrict__ pred, const float* __restrict__ gt,
    const int* __restrict__ s_off, int gbase, int j, int M, int N, int lane,
    unsigned& db, int& off, int& cnt, float2& p01, int& r)
{
    off = s_off[j]; cnt = s_off[j + 1] - off;
    int s = gbase + j;
    p01 = (s < N) ? *(const float2*)(pred + (size_t)s * 6) : make_float2(0.f, 0.f);
    r = off + ((lane < cnt) ? lane : 0);
    r = min(r, M - 1);
}

__global__ void __launch_bounds__(256) k_pass1(
    const float* __restrict__ pred,
    const float* __restrict__ gt,
    const int*   __restrict__ counts,
    int N, int M)
{
    __shared__ int s_off[CHUNK + 1];
    __shared__ int s_wtot[4];
    const int tid  = threadIdx.x;
    const int lane = tid & 31;
    const int gbase = blockIdx.x * CHUNK;

    // local exclusive scan of this block's 128 counts
    if (tid < CHUNK) {
        int w = tid >> 5;
        int g = gbase + tid;
        int c = (g < N) ? counts[g] : 0;
        int inc = c;
        #pragma unroll
        for (int o = 1; o < 32; o <<= 1) {
            int t = __shfl_up_sync(FULL, inc, o);
            if (lane >= o) inc += t;
        }
        if (lane == 31) s_wtot[w] = inc;
        __syncthreads();
        int woff = 0;
        #pragma unroll
        for (int i = 0; i < 4; i++) woff += (i < w) ? s_wtot[i] : 0;
        int cbase = g_cbase[blockIdx.x];
        s_off[tid] = cbase + woff + inc - c;
        if (tid == CHUNK - 1) s_off[CHUNK] = cbase + woff + inc;
    } else {
        __syncthreads();
    }
    __syncthreads();

    // 8 warps x 16 consecutive segments each
    const int wInBlk = tid >> 5;
    const int wbase  = wInBlk * 16;

    #pragma unroll
    for (int k = 0; k < 16; k += 2) {
        unsigned db0, db1; int off0, cnt0, off1, cnt1, r0, r1; float2 p0, p1;
        p1_seg(pred, gt, s_off, gbase, wbase + k,     M, N, lane, db0, off0, cnt0, p0, r0);
        p1_seg(pred, gt, s_off, gbase, wbase + k + 1, M, N, lane, db1, off1, cnt1, p1, r1);

        float2 q0 = *(const float2*)(gt + (size_t)r0 * 6);   // 2 loads in flight
        float2 q1 = *(const float2*)(gt + (size_t)r1 * 6);

        float dx0 = p0.x - q0.x, dy0 = p0.y - q0.y;
        float dx1 = p1.x - q1.x, dy1 = p1.y - q1.y;
        db0 = (lane < cnt0) ? __float_as_uint(dx0 * dx0 + dy0 * dy0) : 0x7f800000u;
        db1 = (lane < cnt1) ? __float_as_uint(dx1 * dx1 + dy1 * dy1) : 0x7f800000u;

        unsigned mn0 = __reduce_min_sync(FULL, db0);
        unsigned mk0 = __ballot_sync(FULL, db0 == mn0);   // lowest lane = ref tie-break
        unsigned mn1 = __reduce_min_sync(FULL, db1);
        unsigned mk1 = __ballot_sync(FULL, db1 == mn1);

        if (lane == 0) {
            int s0 = gbase + wbase + k, s1 = s0 + 1;
            if (s0 < N) g_win[s0] = make_int2(cnt0 > 0 ? off0 + __ffs(mk0) : 0, (int)mn0);
            if (s1 < N) g_win[s1] = make_int2(cnt1 > 0 ? off1 + __ffs(mk1) : 0, (int)mn1);
        }
    }
}

// ------ pass 2: 4 segments/thread, batched loads, losses + finalize -----------
#define P2_UNROLL 4
__global__ void __launch_bounds__(256) k_pass2(
    const float* __restrict__ pred,
    const float* __restrict__ gt,
    float* __restrict__ out,
    int N)
{
    const int lane    = threadIdx.x & 31;
    const int wInBlk  = threadIdx.x >> 5;
    const int tidG    = blockIdx.x * blockDim.x + threadIdx.x;
    const int stride  = gridDim.x * blockDim.x;

    float l0 = 0.f, l1 = 0.f, l2 = 0.f, l3 = 0.f;

    #pragma unroll
    for (int u = 0; u < P2_UNROLL; u++) {
        int s[1]; s[0] = tidG + u * stride;
        // (unrolled manually below for load batching)
    }

    int s0 = tidG;
    int s1 = tidG + stride;
    int s2 = tidG + 2 * stride;
    int s3 = tidG + 3 * stride;

    // batch 1: win records (4 independent loads)
    int2 w0 = (s0 < N) ? g_win[s0] : make_int2(0, 0);
    int2 w1 = (s1 < N) ? g_win[s1] : make_int2(0, 0);
    int2 w2 = (s2 < N) ? g_win[s2] : make_int2(0, 0);
    int2 w3 = (s3 < N) ? g_win[s3] : make_int2(0, 0);

    int r0 = max(w0.x - 1, 0), r1 = max(w1.x - 1, 0);
    int r2 = max(w2.x - 1, 0), r3 = max(w3.x - 1, 0);
    int q0 = (s0 < N) ? s0 : 0, q1 = (s1 < N) ? s1 : 0;
    int q2 = (s2 < N) ? s2 : 0, q3 = (s3 < N) ? s3 : 0;

    // batch 2: 16 independent float2 loads in flight
    const float* pr0 = pred + (size_t)q0 * 6; const float* gr0 = gt + (size_t)r0 * 6;
    const float* pr1 = pred + (size_t)q1 * 6; const float* gr1 = gt + (size_t)r1 * 6;
    const float* pr2 = pred + (size_t)q2 * 6; const float* gr2 = gt + (size_t)r2 * 6;
    const float* pr3 = pred + (size_t)q3 * 6; const float* gr3 = gt + (size_t)r3 * 6;

    float2 pa0 = *(const float2*)(pr0 + 2), pb0 = *(const float2*)(pr0 + 4);
    float2 pa1 = *(const float2*)(pr1 + 2), pb1 = *(const float2*)(pr1 + 4);
    float2 pa2 = *(const float2*)(pr2 + 2), pb2 = *(const float2*)(pr2 + 4);
    float2 pa3 = *(const float2*)(pr3 + 2), pb3 = *(const float2*)(pr3 + 4);
    float2 ga0 = *(const float2*)(gr0 + 2), gb0 = *(const float2*)(gr0 + 4);
    float2 ga1 = *(const float2*)(gr1 + 2), gb1 = *(const float2*)(gr1 + 4);
    float2 ga2 = *(const float2*)(gr2 + 2), gb2 = *(const float2*)(gr2 + 4);
    float2 ga3 = *(const float2*)(gr3 + 2), gb3 = *(const float2*)(gr3 + 4);

    // math (branch-free via flag)
    {
        float f = (s0 < N && w0.x > 0) ? 1.0f : 0.0f;
        float dmin = __uint_as_float((unsigned)w0.y);
        l0 += f * (1.0f - __expf(dmin * (-1.0f / 0.045f)));
        l1 += f * (fabsf(pa0.x - ga0.x) + fabsf(pa0.y - ga0.y));
        float dd = pb0.x - gb0.x, ad = fabsf(dd);
        l2 += f * ((ad < 1.0f) ? 0.5f * dd * dd : ad - 0.5f);
        float x = pb0.y, t = gb0.y;
        if (f > 0.f && t > 0.0f)
            l3 += fmaxf(x, 0.0f) - x * t + __logf(1.0f + __expf(-fabsf(x)));
    }
    {
        float f = (s1 < N && w1.x > 0) ? 1.0f : 0.0f;
        float dmin = __uint_as_float((unsigned)w1.y);
        l0 += f * (1.0f - __expf(dmin * (-1.0f / 0.045f)));
        l1 += f * (fabsf(pa1.x - ga1.x) + fabsf(pa1.y - ga1.y));
        float dd = pb1.x - gb1.x, ad = fabsf(dd);
        l2 += f * ((ad < 1.0f) ? 0.5f * dd * dd : ad - 0.5f);
        float x = pb1.y, t = gb1.y;
        if (f > 0.f && t > 0.0f)
            l3 += fmaxf(x, 0.0f) - x * t + __logf(1.0f + __expf(-fabsf(x)));
    }
    {
        float f = (s2 < N && w2.x > 0) ? 1.0f : 0.0f;
        float dmin = __uint_as_float((unsigned)w2.y);
        l0 += f * (1.0f - __expf(dmin * (-1.0f / 0.045f)));
        l1 += f * (fabsf(pa2.x - ga2.x) + fabsf(pa2.y - ga2.y));
        float dd = pb2.x - gb2.x, ad = fabsf(dd);
        l2 += f * ((ad < 1.0f) ? 0.5f * dd * dd : ad - 0.5f);
        float x = pb2.y, t = gb2.y;
        if (f > 0.f && t > 0.0f)
            l3 += fmaxf(x, 0.0f) - x * t + __logf(1.0f + __expf(-fabsf(x)));
    }
    {
        float f = (s3 < N && w3.x > 0) ? 1.0f : 0.0f;
        float dmin = __uint_as_float((unsigned)w3.y);
        l0 += f * (1.0f - __expf(dmin * (-1.0f / 0.045f)));
        l1 += f * (fabsf(pa3.x - ga3.x) + fabsf(pa3.y - ga3.y));
        float dd = pb3.x - gb3.x, ad = fabsf(dd);
        l2 += f * ((ad < 1.0f) ? 0.5f * dd * dd : ad - 0.5f);
        float x = pb3.y, t = gb3.y;
        if (f > 0.f && t > 0.0f)
            l3 += fmaxf(x, 0.0f) - x * t + __logf(1.0f + __expf(-fabsf(x)));
    }

    // warp reduce
    #pragma unroll
    for (int o = 16; o; o >>= 1) {
        l0 += __shfl_xor_sync(FULL, l0, o);
        l1 += __shfl_xor_sync(FULL, l1, o);
        l2 += __shfl_xor_sync(FULL, l2, o);
        l3 += __shfl_xor_sync(FULL, l3, o);
    }

    __shared__ float sh[8][4];
    if (lane == 0) {
        sh[wInBlk][0] = l0; sh[wInBlk][1] = l1;
        sh[wInBlk][2] = l2; sh[wInBlk][3] = l3;
    }
    __syncthreads();
    if (threadIdx.x == 0) {
        float b0 = 0.f, b1 = 0.f, b2 = 0.f, b3 = 0.f;
        int nw = blockDim.x >> 5;
        for (int w = 0; w < nw; w++) {
            b0 += sh[w][0]; b1 += sh[w][1]; b2 += sh[w][2]; b3 += sh[w][3];
        }
        atomicAdd(&g_acc[0], (double)b0);
        atomicAdd(&g_acc[1], (double)b1);
        atomicAdd(&g_acc[2], (double)b2);
        atomicAdd(&g_acc[3], (double)b3);
        __threadfence();
        int done = atomicAdd(&g_done, 1);
        if (done == (int)gridDim.x - 1) {
            g_done = 0;                               // reset for next replay
            double inv = 1.0 / (double)N;
            double lp = ((volatile double*)g_acc)[0] * inv;
            double la = ((volatile double*)g_acc)[1] * inv;
            double lw = ((volatile double*)g_acc)[2] * inv;
            double ls = ((volatile double*)g_acc)[3] * inv;
            out[0] = (float)lp;
            out[1] = (float)la;
            out[2] = (float)lw;
            out[3] = (float)ls;
            out[4] = (float)(lp + la + lw + 0.5 * ls);
        }
    }
}

extern "C" void kernel_launch(void* const* d_in, const int* in_sizes, int n_in,
                              void* d_out, int out_size) {
    const float* pred   = (const float*)d_in[0];
    const float* gt     = (const float*)d_in[1];
    const int*   counts = (const int*)d_in[2];
    float* out = (float*)d_out;

    int N = in_sizes[2];
    if (N > MAXN) N = MAXN;              // scratch guard (contract: N == 262144)
    int M = in_sizes[1] / 6;             // total gt rows
    int NC = (N + CHUNK - 1) / CHUNK;    // chunks (2048)

    int p2_threads = (N + P2_UNROLL - 1) / P2_UNROLL;      // 65536
    int p2_blocks  = (p2_threads + 255) / 256;             // 256

    k_csum <<<(NC + 7) / 8, 256>>>(counts, N, NC);      // 8 warps/block = 8 chunks
    k_cscan<<<1, 512>>>(NC);
    k_pass1<<<NC, 256>>>(pred, gt, counts, N, M);
    k_pass2<<<p2_blocks, 256>>>(pred, gt, out, N);
}